// round 6
// baseline (speedup 1.0000x reference)
#include <cuda_runtime.h>
#include <cuda_fp16.h>
#include <cstring>

// PositionalSparseLinear: out[b,o] = sum_k x[b, conn[o,k]] * w[o,k]
//   x: [1024,8192] f32   conn: [8192,32] i32   w: [8192,32] f32   out: [1024,8192] f32
//
// Round 6:
//  - fp16-staged transposed SMEM batch tile (BT=8 rows per 16B column), as R5.
//  - Metadata packed as uint4 cw4T[k/4][o] (4 k-steps per 16B), prefetched
//    ALL 32 k into registers via 8 independent coalesced LDG.128 before the
//    gather loop: one exposed L2 latency instead of 32 -> saturate the
//    SMEM crossbar (L1tex), which is the true floor (~28us of gathers).

#define IN_F   8192
#define OUT_F  8192
#define KW     32
#define BATCH  1024
#define BT     8
#define THREADS 1024
#define O_SPLIT 8
#define O_PER_CTA (OUT_F / O_SPLIT)     // 1024 == THREADS
#define SMEM_BYTES (IN_F * BT * (int)sizeof(__half))   // 131072

__device__ uint4 g_cw4T[(KW / 4) * OUT_F];   // [kk][o]: 4 packed (idx<<16|half(w))

static __device__ __forceinline__ __half2 u32_as_h2(unsigned int u) {
    __half2 h; memcpy(&h, &u, sizeof(h)); return h;
}

__global__ void psl_prep(const int* __restrict__ conn, const float* __restrict__ w)
{
    const int idx = blockIdx.x * blockDim.x + threadIdx.x;   // 0 .. (KW/4)*OUT_F-1
    const int kk = idx >> 13;          // / 8192
    const int o  = idx & (OUT_F - 1);  // coalesced writes over o

    unsigned int p[4];
    #pragma unroll
    for (int j = 0; j < 4; j++) {
        const int   c  = conn[(size_t)o * KW + kk * 4 + j];
        const float wv = w   [(size_t)o * KW + kk * 4 + j];
        const unsigned short hb = __half_as_ushort(__float2half_rn(wv));
        p[j] = ((unsigned int)c << 16) | (unsigned int)hb;
    }
    uint4 v; v.x = p[0]; v.y = p[1]; v.z = p[2]; v.w = p[3];
    g_cw4T[(size_t)kk * OUT_F + o] = v;
}

__global__ __launch_bounds__(THREADS, 1)
void psl_main(const float* __restrict__ x, float* __restrict__ out)
{
    extern __shared__ uint4 xs[];   // xs[col] = 8 halves: rows b0..b0+7 of col

    const int tid = threadIdx.x;
    const int b0  = blockIdx.y * BT;

    // ---- Stage: 8 coalesced row-loads per column -> fp16 pack -> STS.128 ----
    const float* xb = x + (size_t)b0 * IN_F;

    #pragma unroll
    for (int c = tid; c < IN_F; c += THREADS) {
        float r0 = xb[c + 0 * (size_t)IN_F];
        float r1 = xb[c + 1 * (size_t)IN_F];
        float r2 = xb[c + 2 * (size_t)IN_F];
        float r3 = xb[c + 3 * (size_t)IN_F];
        float r4 = xb[c + 4 * (size_t)IN_F];
        float r5 = xb[c + 5 * (size_t)IN_F];
        float r6 = xb[c + 6 * (size_t)IN_F];
        float r7 = xb[c + 7 * (size_t)IN_F];

        __half2 h0 = __floats2half2_rn(r0, r1);
        __half2 h1 = __floats2half2_rn(r2, r3);
        __half2 h2 = __floats2half2_rn(r4, r5);
        __half2 h3 = __floats2half2_rn(r6, r7);

        uint4 v;
        memcpy(&v.x, &h0, 4);
        memcpy(&v.y, &h1, 4);
        memcpy(&v.z, &h2, 4);
        memcpy(&v.w, &h3, 4);
        xs[c] = v;
    }
    __syncthreads();

    const int o = blockIdx.x * O_PER_CTA + tid;   // one output per thread
    const uint4* __restrict__ cwp = g_cw4T + o;

    // ---- Prefetch all 32 k of metadata: 8 independent coalesced LDG.128 ----
    uint4 cw[KW / 4];
    #pragma unroll
    for (int kk = 0; kk < KW / 4; kk++)
        cw[kk] = cwp[(size_t)kk * OUT_F];

    float a0 = 0.f, a1 = 0.f, a2 = 0.f, a3 = 0.f;
    float a4 = 0.f, a5 = 0.f, a6 = 0.f, a7 = 0.f;

    #pragma unroll
    for (int kk = 0; kk < KW / 4; kk++) {
        #define PSL_STEP(CW) {                                               \
            const int   c_  = (int)((CW) >> 16);                             \
            const float wv_ = __half2float(__ushort_as_half(                 \
                                  (unsigned short)((CW) & 0xffffu)));        \
            const uint4 hv = xs[c_];                                         \
            float2 f0 = __half22float2(u32_as_h2(hv.x));                     \
            float2 f1 = __half22float2(u32_as_h2(hv.y));                     \
            float2 f2 = __half22float2(u32_as_h2(hv.z));                     \
            float2 f3 = __half22float2(u32_as_h2(hv.w));                     \
            a0 = fmaf(wv_, f0.x, a0);                                        \
            a1 = fmaf(wv_, f0.y, a1);                                        \
            a2 = fmaf(wv_, f1.x, a2);                                        \
            a3 = fmaf(wv_, f1.y, a3);                                        \
            a4 = fmaf(wv_, f2.x, a4);                                        \
            a5 = fmaf(wv_, f2.y, a5);                                        \
            a6 = fmaf(wv_, f3.x, a6);                                        \
            a7 = fmaf(wv_, f3.y, a7);                                        \
        }
        PSL_STEP(cw[kk].x);
        PSL_STEP(cw[kk].y);
        PSL_STEP(cw[kk].z);
        PSL_STEP(cw[kk].w);
        #undef PSL_STEP
    }

    float* op = out + (size_t)b0 * OUT_F + o;
    op[0 * (size_t)OUT_F] = a0;
    op[1 * (size_t)OUT_F] = a1;
    op[2 * (size_t)OUT_F] = a2;
    op[3 * (size_t)OUT_F] = a3;
    op[4 * (size_t)OUT_F] = a4;
    op[5 * (size_t)OUT_F] = a5;
    op[6 * (size_t)OUT_F] = a6;
    op[7 * (size_t)OUT_F] = a7;
}

extern "C" void kernel_launch(void* const* d_in, const int* in_sizes, int n_in,
                              void* d_out, int out_size)
{
    const float* x    = (const float*)d_in[0];   // [1024, 8192] f32
    const int*   conn = (const int*)  d_in[1];   // [8192, 32]   i32
    const float* w    = (const float*)d_in[2];   // [8192, 32]   f32
    float*       out  = (float*)d_out;           // [1024, 8192] f32

    (void)in_sizes; (void)n_in; (void)out_size;

    psl_prep<<<((KW / 4) * OUT_F) / 256, 256>>>(conn, w);

    cudaFuncSetAttribute(psl_main,
                         cudaFuncAttributeMaxDynamicSharedMemorySize,
                         SMEM_BYTES);

    dim3 grid(O_SPLIT, BATCH / BT);   // (8, 128) = 1024 CTAs
    psl_main<<<grid, THREADS, SMEM_BYTES>>>(x, out);
}